// round 2
// baseline (speedup 1.0000x reference)
#include <cuda_runtime.h>
#include <math.h>

#define HW 4096
#define LT 12
#define BATCH 16

// State buffers (allocation-free scratch). h needs ping-pong (spatial halo reads),
// c is updated by exactly the thread that owns that (b,hid,pixel) -> in-place OK.
__device__ float g_h0[2][(size_t)BATCH * 128 * HW];   // 2 x 32 MB
__device__ float g_c0[(size_t)BATCH * 128 * HW];      // 32 MB
__device__ float g_h1[2][(size_t)BATCH * 12 * HW];    // 2 x 3 MB
__device__ float g_c1[(size_t)BATCH * 12 * HW];       // 3 MB

__global__ void fill_zero(float* __restrict__ p, int n) {
    int i = blockIdx.x * blockDim.x + threadIdx.x;
    int stride = gridDim.x * blockDim.x;
    for (; i < n; i += stride) p[i] = 0.0f;
}

__device__ __forceinline__ float fast_sigmoid(float x) {
    // __expf(-x): for very negative x -> inf -> 1/inf = 0 (safe).
    return 1.0f / (1.0f + __expf(-x));
}
__device__ __forceinline__ float fast_tanh_acc(float x) {
    // tanh(x) = 1 - 2/(e^{2x}+1). e -> inf gives 1 (safe), e -> 0 gives -1.
    float e = __expf(2.0f * x);
    return 1.0f - 2.0f / (e + 1.0f);
}

// Fused ConvLSTM step: z = conv3x3(cat(in0, h_prev)) + b; gate math; update c,h.
// Block: 16x16 spatial tile x HB hidden channels x 4 gates, one batch image.
// Thread: 2 hid x 4 gates x 8 px = 64 accumulators.
// CIN = C0 + C1 where C1 = HID (h_prev channels).
template <int CIN, int C0, int HID, int HB, int NHCG>
__global__ void __launch_bounds__(NHCG * 32, 2)
convlstm_step(const float* __restrict__ in0, int in0_bstride,
              const float* __restrict__ in1,   // h_prev, C1 = CIN-C0 channels
              const float* __restrict__ W,     // (4*HID, CIN, 3, 3)
              const float* __restrict__ bias,  // (4*HID)
              float* __restrict__ c_state,     // (B, HID, 64, 64) in/out
              float* __restrict__ h_out)       // (B, HID, 64, 64)
{
    constexpr int THREADS = NHCG * 32;
    constexpr int ICB = 8;
    constexpr int NCHUNK = (CIN + ICB - 1) / ICB;
    constexpr int C1 = CIN - C0;

    __shared__ __align__(16) float si[ICB * 18 * 20];      // input tile + halo, row pad 20
    __shared__ __align__(16) float sw[ICB * 9 * HB * 4];   // [ci][tap][hc][gate]

    const int tid  = threadIdx.x;
    const int pg   = tid & 31;     // pixel group (32): 16 rows x 2 col-octs
    const int hg   = tid >> 5;     // hid group (NHCG): owns hc = hg, hg+NHCG
    const int row  = pg >> 1;
    const int colg = pg & 1;
    const int ty0  = (blockIdx.x >> 2) << 4;
    const int tx0  = (blockIdx.x & 3) << 4;
    const int hid0 = blockIdx.y * HB;
    const int b    = blockIdx.z;

    const float* in0b = in0 + (size_t)b * in0_bstride;
    const float* in1b = in1 + (size_t)b * C1 * HW;

    float acc[2][4][8];
#pragma unroll
    for (int tc = 0; tc < 2; ++tc)
#pragma unroll
        for (int g = 0; g < 4; ++g)
#pragma unroll
            for (int j = 0; j < 8; ++j) acc[tc][g][j] = 0.0f;

    for (int ch = 0; ch < NCHUNK; ++ch) {
        const int ic0 = ch * ICB;
        // ---- load input tile (8 ch x 18x18 with halo, zero-pad edges/overrun)
        for (int idx = tid; idx < ICB * 18 * 18; idx += THREADS) {
            int ci  = idx / 324;
            int rem = idx - ci * 324;
            int r   = rem / 18;
            int c   = rem - r * 18;
            int cg  = ic0 + ci;
            int gy  = ty0 - 1 + r;
            int gx  = tx0 - 1 + c;
            float v = 0.0f;
            if (cg < CIN && (unsigned)gy < 64u && (unsigned)gx < 64u) {
                v = (cg < C0) ? __ldg(&in0b[(size_t)cg * HW + gy * 64 + gx])
                              : __ldg(&in1b[(size_t)(cg - C0) * HW + gy * 64 + gx]);
            }
            si[ci * 360 + r * 20 + c] = v;
        }
        // ---- load weight slab: sw[((ci*9+tap)*HB + hc)*4 + g]
        for (int idx = tid; idx < ICB * 9 * HB * 4; idx += THREADS) {
            int g   = idx & 3;
            int t2  = idx >> 2;
            int hc  = t2 % HB;
            int t3  = t2 / HB;
            int tap = t3 % 9;
            int ci  = t3 / 9;
            int cg  = ic0 + ci;
            float wv = 0.0f;
            if (cg < CIN) {
                int oc = g * HID + hid0 + hc;
                wv = __ldg(&W[((size_t)oc * CIN + cg) * 9 + tap]);
            }
            sw[idx] = wv;
        }
        __syncthreads();

        // ---- compute: 576 FFMA / thread / chunk, 27 vector LDS
#pragma unroll
        for (int ci = 0; ci < ICB; ++ci) {
            const float* sib = &si[ci * 360 + row * 20 + colg * 8];
#pragma unroll
            for (int dy = 0; dy < 3; ++dy) {
                float r0[10];
                const float4 a0 = *(const float4*)(sib + dy * 20);
                const float4 a1 = *(const float4*)(sib + dy * 20 + 4);
                const float2 a2 = *(const float2*)(sib + dy * 20 + 8);
                r0[0] = a0.x; r0[1] = a0.y; r0[2] = a0.z; r0[3] = a0.w;
                r0[4] = a1.x; r0[5] = a1.y; r0[6] = a1.z; r0[7] = a1.w;
                r0[8] = a2.x; r0[9] = a2.y;
#pragma unroll
                for (int dx = 0; dx < 3; ++dx) {
                    const int tap = dy * 3 + dx;
                    const float* wb = &sw[((ci * 9 + tap) * HB + hg) * 4];
                    const float4 w0 = *(const float4*)wb;
                    const float4 w1 = *(const float4*)(wb + NHCG * 4);
#pragma unroll
                    for (int j = 0; j < 8; ++j) {
                        const float v = r0[dx + j];
                        acc[0][0][j] = fmaf(w0.x, v, acc[0][0][j]);
                        acc[0][1][j] = fmaf(w0.y, v, acc[0][1][j]);
                        acc[0][2][j] = fmaf(w0.z, v, acc[0][2][j]);
                        acc[0][3][j] = fmaf(w0.w, v, acc[0][3][j]);
                        acc[1][0][j] = fmaf(w1.x, v, acc[1][0][j]);
                        acc[1][1][j] = fmaf(w1.y, v, acc[1][1][j]);
                        acc[1][2][j] = fmaf(w1.z, v, acc[1][2][j]);
                        acc[1][3][j] = fmaf(w1.w, v, acc[1][3][j]);
                    }
                }
            }
        }
        __syncthreads();
    }

    // ---- epilogue: bias + gates + state update
#pragma unroll
    for (int tc = 0; tc < 2; ++tc) {
        const int hch = hid0 + hg + tc * NHCG;
        const float bi = bias[0 * HID + hch];
        const float bf = bias[1 * HID + hch];
        const float bo = bias[2 * HID + hch];
        const float bg = bias[3 * HID + hch];
        const int gy  = ty0 + row;
        const int gxb = tx0 + colg * 8;
        const size_t base = ((size_t)b * HID + hch) * HW + gy * 64 + gxb;
#pragma unroll
        for (int j = 0; j < 8; ++j) {
            const float zi = acc[tc][0][j] + bi;
            const float zf = acc[tc][1][j] + bf;
            const float zo = acc[tc][2][j] + bo;
            const float zg = acc[tc][3][j] + bg;
            const float cp = c_state[base + j];
            const float cn = fast_sigmoid(zf) * cp + fast_sigmoid(zi) * fast_tanh_acc(zg);
            const float hn = fast_sigmoid(zo) * fast_tanh_acc(cn);
            c_state[base + j] = cn;
            h_out[base + j]   = hn;
        }
    }
}

extern "C" void kernel_launch(void* const* d_in, const int* in_sizes, int n_in,
                              void* d_out, int out_size) {
    const float* hist = (const float*)d_in[0];
    const float* W0   = (const float*)d_in[2];
    const float* b0   = (const float*)d_in[3];
    const float* W1   = (const float*)d_in[4];
    const float* b1   = (const float*)d_in[5];
    float* out = (float*)d_out;

    float *h0p, *c0p, *h1p, *c1p;
    cudaGetSymbolAddress((void**)&h0p, g_h0);
    cudaGetSymbolAddress((void**)&c0p, g_c0);
    cudaGetSymbolAddress((void**)&h1p, g_h1);
    cudaGetSymbolAddress((void**)&c1p, g_c1);

    const size_t n_s0 = (size_t)BATCH * 128 * HW;   // one h0 buffer
    const size_t n_s1 = (size_t)BATCH * 12 * HW;    // one h1 buffer

    // Reset recurrent state every call (graph replays must be deterministic).
    fill_zero<<<1024, 256>>>(h0p, (int)n_s0);   // g_h0[0]
    fill_zero<<<1024, 256>>>(c0p, (int)n_s0);
    fill_zero<<<64,   256>>>(h1p, (int)n_s1);   // g_h1[0]
    fill_zero<<<64,   256>>>(c1p, (int)n_s1);

    dim3 grid0(16, 8, BATCH), blk0(256);   // 128 hid / 16 per block
    dim3 grid1(16, 1, BATCH), blk1(192);   // 12 hid in one block row

    for (int t = 0; t < LT; ++t) {
        const float* h0_prev = h0p + (size_t)(t & 1) * n_s0;
        float*       h0_next = h0p + (size_t)((t + 1) & 1) * n_s0;
        const float* h1_prev = h1p + (size_t)(t & 1) * n_s1;
        float*       h1_next = (t == LT - 1) ? out : (h1p + (size_t)((t + 1) & 1) * n_s1);

        // Layer 0: cat(x_t [1ch], h0 [128ch]) -> 512 gate channels
        convlstm_step<129, 1, 128, 16, 8><<<grid0, blk0>>>(
            hist + t * HW, LT * HW, h0_prev, W0, b0, c0p, h0_next);
        // Layer 1: cat(h0_t [128ch], h1 [12ch]) -> 48 gate channels
        convlstm_step<140, 128, 12, 12, 6><<<grid1, blk1>>>(
            h0_next, 128 * HW, h1_prev, W1, b1, c1p, h1_next);
    }
}